// round 13
// baseline (speedup 1.0000x reference)
#include <cuda_runtime.h>

#define FINF __int_as_float(0x7f800000)

constexpr int BB = 32, HH = 512, WW = 512;
constexpr int TX = 128;           // tile width (outputs)
constexpr int TY = 64;            // tile height (outputs)
constexpr int R  = 7;             // k=15 radius
constexpr int DY = TY + 2 * R;    // 78 halo rows
constexpr int NT = 256;           // 8 warps

__device__ __forceinline__ float cmin3(float a, float b, float c) {
    return fminf(fminf(a, b), c);
}

__device__ __forceinline__ float4 cmin4x3(float4 a, float4 c, float4 f) {
    float4 r;
    r.x = cmin3(a.x, c.x, f.x);
    r.y = cmin3(a.y, c.y, f.y);
    r.z = cmin3(a.z, c.z, f.z);
    r.w = cmin3(a.w, c.w, f.w);
    return r;
}

// Horizontal 15-tap min for 4 outputs/lane from own block d, left-edge block gv
// (valid on lanes 0-1), right-edge block ev (valid on lanes 30-31). Whole-warp.
__device__ __forceinline__ float4 hwin(float4 d, float4 gv, float4 ev, int lane) {
    const float P0 = d.x;
    const float P1 = fminf(P0, d.y);
    const float P2 = fminf(P1, d.z);
    const float F  = fminf(P2, d.w);
    const float S3 = d.w;
    const float S2 = fminf(d.z, S3);
    const float S1 = fminf(d.y, S2);

    const float gS3 = gv.w;
    const float gS2 = fminf(gv.z, gS3);
    const float gS1 = fminf(gv.y, gS2);
    const float gF  = fminf(gv.x, gS1);
    const float eP0 = ev.x;
    const float eP1 = fminf(eP0, ev.y);
    const float eP2 = fminf(eP1, ev.z);
    const float eF  = fminf(eP2, ev.w);

    const unsigned m = 0xffffffffu;
    const float upF   = __shfl_up_sync(m, F, 1);     // full(i-1)
    const float dnF   = __shfl_down_sync(m, F, 1);   // full(i+1)
    const float dn_gF = __shfl_down_sync(m, gF, 1);  // lane1's gF -> lane0
    const float up_eF = __shfl_up_sync(m, eF, 1);    // lane30's eF -> lane31
    const float upS1  = __shfl_up_sync(m, S1, 2);    // suffix(i-2)
    const float upS2  = __shfl_up_sync(m, S2, 2);
    const float upS3  = __shfl_up_sync(m, S3, 2);
    const float dnP0  = __shfl_down_sync(m, P0, 2);  // prefix(i+2)
    const float dnP1  = __shfl_down_sync(m, P1, 2);
    const float dnP2  = __shfl_down_sync(m, P2, 2);

    const float FL1 = (lane == 0)  ? dn_gF : upF;
    const float FR  = (lane == 31) ? up_eF : dnF;
    const float Sg1 = (lane < 2)  ? gS1 : upS1;
    const float Sg2 = (lane < 2)  ? gS2 : upS2;
    const float Sg3 = (lane < 2)  ? gS3 : upS3;
    const float Q0  = (lane >= 30) ? eP0 : dnP0;
    const float Q1  = (lane >= 30) ? eP1 : dnP1;
    const float Q2  = (lane >= 30) ? eP2 : dnP2;

    const float core = cmin3(FL1, F, FR);
    float4 o;
    o.x = fminf(core, Sg1);               // window [x0-7 , x0+7 ]
    o.y = fminf(fminf(core, Sg2), Q0);    // window [x0-6 , x0+8 ]
    o.z = fminf(fminf(core, Sg3), Q1);    // window [x0-5 , x0+9 ]
    o.w = fminf(core, Q2);                // window [x0-4 , x0+10]
    return o;
}

__global__ __launch_bounds__(NT) void dark_erode(const float* __restrict__ I,
                                                 float* __restrict__ O) {
    __shared__ float hs[DY * TX];  // horizontally-eroded halo tile, pitch 128

    const int tid  = threadIdx.x;
    const int lane = tid & 31;
    const int warp = tid >> 5;
    const int bx = blockIdx.x, by = blockIdx.y, b = blockIdx.z;
    const int W0 = bx * TX;
    const int x0 = W0 + 4 * lane;          // own 4-float block
    const float* base = I + (size_t)b * 3 * HH * WW;
    const bool is_gl = (lane < 2)   && (x0 - 8 >= 0);   // left-edge halo loader
    const bool is_el = (lane >= 30) && (x0 + 8 < WW);   // right-edge halo loader
    const float4 INF4 = make_float4(FINF, FINF, FINF, FINF);

    // ---- Phase A: 2-row software-pipelined horizontal pass ----
    // Warp w handles row pairs (w+16k, w+16k+8); the 6 main LDG.128s of a pair
    // are independent -> double MLP vs single-row.
    for (int r = warp; r < DY; r += 16) {
        const int r2   = r + 8;
        const bool has2 = (r2 < DY);                  // warp-uniform
        const int gy1 = by * TY - R + r;
        const int gy2 = gy1 + 8;
        const bool v1 = (unsigned)gy1 < (unsigned)HH;
        const bool v2 = has2 && ((unsigned)gy2 < (unsigned)HH);

        // ---- batched loads, both rows ----
        float4 a1 = INF4, c1 = INF4, f1 = INF4;
        float4 a2 = INF4, c2 = INF4, f2 = INF4;
        const float* p1 = base + (size_t)gy1 * WW + x0;
        const float* p2 = base + (size_t)gy2 * WW + x0;
        if (v1) {
            a1 = *(const float4*)(p1);
            c1 = *(const float4*)(p1 + HH * WW);
            f1 = *(const float4*)(p1 + 2 * HH * WW);
        }
        if (v2) {
            a2 = *(const float4*)(p2);
            c2 = *(const float4*)(p2 + HH * WW);
            f2 = *(const float4*)(p2 + 2 * HH * WW);
        }
        float4 g1 = INF4, g2 = INF4, e1 = INF4, e2 = INF4;
        if (is_gl) {
            if (v1) g1 = cmin4x3(*(const float4*)(p1 - 8),
                                 *(const float4*)(p1 - 8 + HH * WW),
                                 *(const float4*)(p1 - 8 + 2 * HH * WW));
            if (v2) g2 = cmin4x3(*(const float4*)(p2 - 8),
                                 *(const float4*)(p2 - 8 + HH * WW),
                                 *(const float4*)(p2 - 8 + 2 * HH * WW));
        }
        if (is_el) {
            if (v1) e1 = cmin4x3(*(const float4*)(p1 + 8),
                                 *(const float4*)(p1 + 8 + HH * WW),
                                 *(const float4*)(p1 + 8 + 2 * HH * WW));
            if (v2) e2 = cmin4x3(*(const float4*)(p2 + 8),
                                 *(const float4*)(p2 + 8 + HH * WW),
                                 *(const float4*)(p2 + 8 + 2 * HH * WW));
        }

        const float4 d1 = cmin4x3(a1, c1, f1);
        const float4 d2 = cmin4x3(a2, c2, f2);

        const float4 o1 = hwin(d1, g1, e1, lane);
        *(float4*)(hs + r * TX + 4 * lane) = o1;
        const float4 o2 = hwin(d2, g2, e2, lane);   // whole-warp; has2 uniform
        if (has2) *(float4*)(hs + r2 * TX + 4 * lane) = o2;
    }
    __syncthreads();

    // ---- Phase B: vertical 15-tap min from smem, coalesced output ----
    for (int t = tid; t < TX * (TY / 8); t += NT) {
        const int lx = t & (TX - 1);
        const int yg = t >> 7;                 // TX = 128
        const float* cp = hs + (yg * 8) * TX + lx;

        float w[22];
#pragma unroll
        for (int i = 0; i < 22; i++) w[i] = cp[i * TX];
#pragma unroll
        for (int i = 0; i < 21; i++) w[i] = fminf(w[i], w[i + 1]);
#pragma unroll
        for (int i = 0; i < 19; i++) w[i] = fminf(w[i], w[i + 2]);
#pragma unroll
        for (int i = 0; i < 15; i++) w[i] = fminf(w[i], w[i + 4]);

        float* op = O + ((size_t)b * HH + by * TY + yg * 8) * WW + W0 + lx;
#pragma unroll
        for (int j = 0; j < 8; j++) {
            op[(size_t)j * WW] = fminf(w[j], w[j + 7]);
        }
    }
}

extern "C" void kernel_launch(void* const* d_in, const int* in_sizes, int n_in,
                              void* d_out, int out_size) {
    // Find I by element count (robust to metadata ordering; k=15 baked in).
    const float* I = (const float*)d_in[0];
    for (int i = 0; i < n_in; i++) {
        if (in_sizes[i] == BB * 3 * HH * WW) I = (const float*)d_in[i];
    }
    float* out = (float*)d_out;

    dim3 grid(WW / TX, HH / TY, BB);   // (4, 8, 32) = 1024 blocks
    dark_erode<<<grid, NT>>>(I, out);
}

// round 15
// speedup vs baseline: 1.1168x; 1.1168x over previous
#include <cuda_runtime.h>

#define FINF __int_as_float(0x7f800000)

constexpr int BB = 32, HH = 512, WW = 512;
constexpr int TX = 128;           // tile width (outputs)
constexpr int TY = 64;            // tile height (outputs)
constexpr int R  = 7;             // k=15 radius
constexpr int DY = TY + 2 * R;    // 78 halo rows
constexpr int NT = 256;           // 8 warps

__device__ __forceinline__ float cmin3(float a, float b, float c) {
    return fminf(fminf(a, b), c);
}

__device__ __forceinline__ float4 cmin4x3(float4 a, float4 c, float4 f) {
    float4 r;
    r.x = cmin3(a.x, c.x, f.x);
    r.y = cmin3(a.y, c.y, f.y);
    r.z = cmin3(a.z, c.z, f.z);
    r.w = cmin3(a.w, c.w, f.w);
    return r;
}

// Horizontal 15-tap min for 4 outputs/lane from own block d, left-edge block gv
// (valid on lanes 0-1), right-edge block ev (valid on lanes 30-31). Whole-warp.
__device__ __forceinline__ float4 hwin(float4 d, float4 gv, float4 ev, int lane) {
    const float P0 = d.x;
    const float P1 = fminf(P0, d.y);
    const float P2 = fminf(P1, d.z);
    const float F  = fminf(P2, d.w);
    const float S3 = d.w;
    const float S2 = fminf(d.z, S3);
    const float S1 = fminf(d.y, S2);

    const float gS3 = gv.w;
    const float gS2 = fminf(gv.z, gS3);
    const float gS1 = fminf(gv.y, gS2);
    const float gF  = fminf(gv.x, gS1);
    const float eP0 = ev.x;
    const float eP1 = fminf(eP0, ev.y);
    const float eP2 = fminf(eP1, ev.z);
    const float eF  = fminf(eP2, ev.w);

    const unsigned m = 0xffffffffu;
    const float upF   = __shfl_up_sync(m, F, 1);     // full(i-1)
    const float dnF   = __shfl_down_sync(m, F, 1);   // full(i+1)
    const float dn_gF = __shfl_down_sync(m, gF, 1);  // lane1's gF -> lane0
    const float up_eF = __shfl_up_sync(m, eF, 1);    // lane30's eF -> lane31
    const float upS1  = __shfl_up_sync(m, S1, 2);    // suffix(i-2)
    const float upS2  = __shfl_up_sync(m, S2, 2);
    const float upS3  = __shfl_up_sync(m, S3, 2);
    const float dnP0  = __shfl_down_sync(m, P0, 2);  // prefix(i+2)
    const float dnP1  = __shfl_down_sync(m, P1, 2);
    const float dnP2  = __shfl_down_sync(m, P2, 2);

    const float FL1 = (lane == 0)  ? dn_gF : upF;
    const float FR  = (lane == 31) ? up_eF : dnF;
    const float Sg1 = (lane < 2)  ? gS1 : upS1;
    const float Sg2 = (lane < 2)  ? gS2 : upS2;
    const float Sg3 = (lane < 2)  ? gS3 : upS3;
    const float Q0  = (lane >= 30) ? eP0 : dnP0;
    const float Q1  = (lane >= 30) ? eP1 : dnP1;
    const float Q2  = (lane >= 30) ? eP2 : dnP2;

    const float core = cmin3(FL1, F, FR);
    float4 o;
    o.x = fminf(core, Sg1);               // window [x0-7 , x0+7 ]
    o.y = fminf(fminf(core, Sg2), Q0);    // window [x0-6 , x0+8 ]
    o.z = fminf(fminf(core, Sg3), Q1);    // window [x0-5 , x0+9 ]
    o.w = fminf(core, Q2);                // window [x0-4 , x0+10]
    return o;
}

__global__ __launch_bounds__(NT, 4) void dark_erode(const float* __restrict__ I,
                                                    float* __restrict__ O) {
    __shared__ float hs[DY * TX];  // horizontally-eroded halo tile, pitch 128

    const int tid  = threadIdx.x;
    const int lane = tid & 31;
    const int warp = tid >> 5;
    const int bx = blockIdx.x, by = blockIdx.y, b = blockIdx.z;
    const int W0 = bx * TX;
    const int x0 = W0 + 4 * lane;          // own 4-float block
    const float* base = I + (size_t)b * 3 * HH * WW;
    const bool is_gl = (lane < 2)   && (x0 - 8 >= 0);   // left-edge halo loader
    const bool is_el = (lane >= 30) && (x0 + 8 < WW);   // right-edge halo loader
    const float4 INF4 = make_float4(FINF, FINF, FINF, FINF);

    // ---- Phase A: load-ahead pipelined horizontal pass ----
    // Warp w handles rows w, w+8, ... While computing row r, the 3 main
    // LDG.128s of row r+8 are already in flight (MLP 6 steady-state).
    {
        int gy = by * TY - R + warp;
        bool v = (unsigned)gy < (unsigned)HH;
        const float* p = base + (size_t)gy * WW + x0;

        float4 a = INF4, c = INF4, f = INF4;
        if (v) {
            a = *(const float4*)(p);
            c = *(const float4*)(p + HH * WW);
            f = *(const float4*)(p + 2 * HH * WW);
        }

        for (int r = warp; r < DY; r += 8) {
            // prefetch next row's main blocks
            const int gyn = gy + 8;
            const bool vn = (r + 8 < DY) && ((unsigned)gyn < (unsigned)HH);
            const float* pn = p + 8 * WW;
            float4 an = INF4, cn = INF4, fn = INF4;
            if (vn) {
                an = *(const float4*)(pn);
                cn = *(const float4*)(pn + HH * WW);
                fn = *(const float4*)(pn + 2 * HH * WW);
            }

            // current row edge blocks (4 lanes only, mostly L2-hits)
            float4 gv = INF4, ev = INF4;
            if (v && is_gl) {
                gv = cmin4x3(*(const float4*)(p - 8),
                             *(const float4*)(p - 8 + HH * WW),
                             *(const float4*)(p - 8 + 2 * HH * WW));
            }
            if (v && is_el) {
                ev = cmin4x3(*(const float4*)(p + 8),
                             *(const float4*)(p + 8 + HH * WW),
                             *(const float4*)(p + 8 + 2 * HH * WW));
            }

            const float4 d = cmin4x3(a, c, f);
            const float4 o = hwin(d, gv, ev, lane);
            *(float4*)(hs + r * TX + 4 * lane) = o;

            // rotate pipeline
            a = an; c = cn; f = fn;
            v = vn; gy = gyn; p = pn;
        }
    }
    __syncthreads();

    // ---- Phase B: vertical 15-tap min from smem, coalesced output ----
    for (int t = tid; t < TX * (TY / 8); t += NT) {
        const int lx = t & (TX - 1);
        const int yg = t >> 7;                 // TX = 128
        const float* cp = hs + (yg * 8) * TX + lx;

        float w[22];
#pragma unroll
        for (int i = 0; i < 22; i++) w[i] = cp[i * TX];
#pragma unroll
        for (int i = 0; i < 21; i++) w[i] = fminf(w[i], w[i + 1]);
#pragma unroll
        for (int i = 0; i < 19; i++) w[i] = fminf(w[i], w[i + 2]);
#pragma unroll
        for (int i = 0; i < 15; i++) w[i] = fminf(w[i], w[i + 4]);

        float* op = O + ((size_t)b * HH + by * TY + yg * 8) * WW + W0 + lx;
#pragma unroll
        for (int j = 0; j < 8; j++) {
            op[(size_t)j * WW] = fminf(w[j], w[j + 7]);
        }
    }
}

extern "C" void kernel_launch(void* const* d_in, const int* in_sizes, int n_in,
                              void* d_out, int out_size) {
    // Find I by element count (robust to metadata ordering; k=15 baked in).
    const float* I = (const float*)d_in[0];
    for (int i = 0; i < n_in; i++) {
        if (in_sizes[i] == BB * 3 * HH * WW) I = (const float*)d_in[i];
    }
    float* out = (float*)d_out;

    dim3 grid(WW / TX, HH / TY, BB);   // (4, 8, 32) = 1024 blocks
    dark_erode<<<grid, NT>>>(I, out);
}